// round 2
// baseline (speedup 1.0000x reference)
#include <cuda_runtime.h>
#include <cuda_bf16.h>
#include <math.h>

// ---------------- problem constants ----------------
#define NUM_ENVS   16384
#define NUM_AGENTS 16
#define IN_DIM     128
#define GCN_H      64
#define RNN_H      64
#define E_PER      128
#define OUT_DIM    512          // 16*4*8
#define LOGITS_ELEMS (NUM_ENVS * OUT_DIM)          // 8388608
#define HNEW_ELEMS   (NUM_ENVS * NUM_AGENTS * RNN_H) // 16777216

// scratch for h_new in case d_out only holds logits
__device__ float g_hscratch[HNEW_ELEMS];
__device__ int   g_edge_is_i64;

// ---------------- edge dtype detection ----------------
// If edge_index is int64 (values < 16), every odd int32 word is 0.
__global__ void detect_edge_dtype_kernel(const int* __restrict__ e) {
    __shared__ int allzero;
    if (threadIdx.x == 0) allzero = 1;
    __syncthreads();
    int bad = 0;
    for (int i = threadIdx.x; i < 2048; i += 256)
        if (e[2 * i + 1] != 0) bad = 1;
    if (bad) allzero = 0;
    __syncthreads();
    if (threadIdx.x == 0) g_edge_is_i64 = allzero;
}

// ---------------- kernel A: GCN + GRU ----------------
struct SmemA {
    float Wg[IN_DIM * GCN_H];        // [k][f] row-major, 8192
    float WihT[GCN_H * 193];         // [k][j], pitch 193 (conflict-free)
    float WhhT[RNN_H * 193];
    float bg[GCN_H];
    float bih[192];
    float bhh[192];
    float x[NUM_AGENTS * IN_DIM];    // 2048
    float xw[NUM_AGENTS * GCN_H];    // 1024 (reused as gcn_out)
    float agg[NUM_AGENTS * GCN_H];   // 1024
    float h[NUM_AGENTS * RNN_H];     // 1024
    float G[NUM_AGENTS * 128];       // r,z pre-activations
    float Nx[NUM_AGENTS * RNN_H];
    float Nh[NUM_AGENTS * RNN_H];
    float deg[NUM_AGENTS];
    float dinv[NUM_AGENTS];
    float invdeg[NUM_AGENTS];
    float norm[E_PER];
    int   row[E_PER];
    int   col[E_PER];
};

__global__ __launch_bounds__(512, 1)
void gcn_gru_kernel(const float* __restrict__ x_g,
                    const void*  __restrict__ edges,
                    const float* __restrict__ prevh,
                    const float* __restrict__ Wg_g,
                    const float* __restrict__ bg_g,
                    const float* __restrict__ Wih_g,
                    const float* __restrict__ Whh_g,
                    const float* __restrict__ bih_g,
                    const float* __restrict__ bhh_g,
                    float* __restrict__ hnew_out)
{
    extern __shared__ unsigned char smem_raw[];
    SmemA& s = *reinterpret_cast<SmemA*>(smem_raw);
    const int tid = threadIdx.x;   // 512 threads

    // ---- load weights once per block ----
    for (int i = tid; i < IN_DIM * GCN_H; i += 512) s.Wg[i] = Wg_g[i];
    for (int i = tid; i < 192 * 64; i += 512) {
        int j = i >> 6, k = i & 63;               // W[j][k]
        s.WihT[k * 193 + j] = Wih_g[i];
        s.WhhT[k * 193 + j] = Whh_g[i];
    }
    if (tid < 64)  s.bg[tid]  = bg_g[tid];
    if (tid < 192) { s.bih[tid] = bih_g[tid]; s.bhh[tid] = bhh_g[tid]; }
    const int is64 = g_edge_is_i64;
    __syncthreads();

    for (int env = blockIdx.x; env < NUM_ENVS; env += gridDim.x) {
        // ---- load x, h, edges; init deg/agg ----
        {
            const float4* xg = (const float4*)(x_g + (size_t)env * (NUM_AGENTS * IN_DIM));
            ((float4*)s.x)[tid] = xg[tid];                     // 512 float4 = 2048 f
            const float4* hg = (const float4*)(prevh + (size_t)env * (NUM_AGENTS * RNN_H));
            if (tid < 256) ((float4*)s.h)[tid] = hg[tid];
        }
        if (tid < NUM_AGENTS) s.deg[tid] = 1.0f;               // self loop
        if (tid < E_PER) {
            size_t base = (size_t)env * (2 * E_PER);
            int r, c;
            if (is64) {
                const long long* e = (const long long*)edges;
                r = (int)e[base + tid]; c = (int)e[base + E_PER + tid];
            } else {
                const int* e = (const int*)edges;
                r = e[base + tid]; c = e[base + E_PER + tid];
            }
            s.row[tid] = r; s.col[tid] = c;
        }
        for (int i = tid; i < NUM_AGENTS * GCN_H; i += 512) s.agg[i] = 0.0f;
        __syncthreads();

        if (tid < E_PER) atomicAdd(&s.deg[s.col[tid]], 1.0f);

        // ---- xw = x @ W_gcn : 2 outputs per thread (ILP 2) ----
        {
            int f = tid & 63, n = tid >> 6;       // n in 0..7
            const float* x0 = &s.x[n * IN_DIM];
            const float* x1 = &s.x[(n + 8) * IN_DIM];
            float a0 = 0.f, a1 = 0.f;
            #pragma unroll 16
            for (int k = 0; k < IN_DIM; k++) {
                float w = s.Wg[k * GCN_H + f];
                a0 += x0[k] * w;
                a1 += x1[k] * w;
            }
            s.xw[tid]       = a0;
            s.xw[tid + 512] = a1;
        }
        __syncthreads();   // xw + deg ready

        if (tid < NUM_AGENTS) {
            float d = s.deg[tid];
            s.dinv[tid]   = rsqrtf(d);
            s.invdeg[tid] = 1.0f / d;
        }
        __syncthreads();
        if (tid < E_PER) s.norm[tid] = s.dinv[s.row[tid]] * s.dinv[s.col[tid]];
        __syncthreads();

        // ---- scatter: agg[col] += norm * xw[row] ----
        for (int idx = tid; idx < E_PER * GCN_H; idx += 512) {
            int e = idx >> 6, f = idx & 63;
            atomicAdd(&s.agg[s.col[e] * GCN_H + f], s.norm[e] * s.xw[s.row[e] * GCN_H + f]);
        }
        __syncthreads();

        // ---- gcn_out = agg + xw/deg + b (reuse xw buffer) ----
        for (int o = tid; o < NUM_AGENTS * GCN_H; o += 512) {
            int n = o >> 6, f = o & 63;
            s.xw[o] = s.agg[o] + s.xw[o] * s.invdeg[n] + s.bg[f];
        }
        __syncthreads();

        // ---- GRU gate GEMMs: 16 nodes x 192 gates ----
        for (int idx = tid; idx < NUM_AGENTS * 192; idx += 512) {
            int n = idx / 192, j = idx % 192;
            const float* g  = &s.xw[n * GCN_H];
            const float* hh = &s.h[n * RNN_H];
            float ax = 0.f, ah = 0.f;
            #pragma unroll 8
            for (int k = 0; k < 64; k++) {
                ax += g[k]  * s.WihT[k * 193 + j];
                ah += hh[k] * s.WhhT[k * 193 + j];
            }
            ax += s.bih[j];
            ah += s.bhh[j];
            if (j < 128) s.G[n * 128 + j] = ax + ah;
            else {
                s.Nx[n * 64 + (j - 128)] = ax;
                s.Nh[n * 64 + (j - 128)] = ah;
            }
        }
        __syncthreads();

        // ---- combine gates, write h_new ----
        float* outp = hnew_out + (size_t)env * (NUM_AGENTS * RNN_H);
        for (int o = tid; o < NUM_AGENTS * RNN_H; o += 512) {
            int n = o >> 6, f = o & 63;
            float r  = 1.0f / (1.0f + __expf(-s.G[n * 128 + f]));
            float z  = 1.0f / (1.0f + __expf(-s.G[n * 128 + 64 + f]));
            float nn = tanhf(s.Nx[o] + r * s.Nh[o]);
            float hv = s.h[o];
            outp[o] = (1.0f - z) * nn + z * hv;
        }
        __syncthreads();  // protect smem before next env
    }
}

// ---------------- kernel B: logits = h_new @ W_lin^T + b ----------------
// C[16384,512] = A[16384,1024] * W[512,1024]^T
#define BM 128
#define BN 128
#define BK 16

__global__ __launch_bounds__(256)
void logits_gemm_kernel(const float* __restrict__ A,
                        const float* __restrict__ W,
                        const float* __restrict__ bias,
                        float* __restrict__ C)
{
    __shared__ float sA[BK][BM];
    __shared__ float sB[BK][BN];

    const int tid = threadIdx.x;
    const int m0 = blockIdx.x * BM;
    const int n0 = blockIdx.y * BN;
    const int tx = tid & 15;          // output-col group
    const int ty = tid >> 4;          // output-row group

    const int lrow = tid >> 2;        // 0..63
    const int lk   = (tid & 3) * 4;   // 0,4,8,12

    float acc[8][8];
    #pragma unroll
    for (int i = 0; i < 8; i++)
        #pragma unroll
        for (int j = 0; j < 8; j++) acc[i][j] = 0.0f;

    for (int k0 = 0; k0 < NUM_AGENTS * RNN_H; k0 += BK) {
        float4 av0 = *(const float4*)&A[(size_t)(m0 + lrow)      * 1024 + k0 + lk];
        float4 av1 = *(const float4*)&A[(size_t)(m0 + lrow + 64) * 1024 + k0 + lk];
        float4 bv0 = *(const float4*)&W[(size_t)(n0 + lrow)      * 1024 + k0 + lk];
        float4 bv1 = *(const float4*)&W[(size_t)(n0 + lrow + 64) * 1024 + k0 + lk];
        __syncthreads();
        sA[lk + 0][lrow] = av0.x; sA[lk + 1][lrow] = av0.y;
        sA[lk + 2][lrow] = av0.z; sA[lk + 3][lrow] = av0.w;
        sA[lk + 0][lrow + 64] = av1.x; sA[lk + 1][lrow + 64] = av1.y;
        sA[lk + 2][lrow + 64] = av1.z; sA[lk + 3][lrow + 64] = av1.w;
        sB[lk + 0][lrow] = bv0.x; sB[lk + 1][lrow] = bv0.y;
        sB[lk + 2][lrow] = bv0.z; sB[lk + 3][lrow] = bv0.w;
        sB[lk + 0][lrow + 64] = bv1.x; sB[lk + 1][lrow + 64] = bv1.y;
        sB[lk + 2][lrow + 64] = bv1.z; sB[lk + 3][lrow + 64] = bv1.w;
        __syncthreads();

        #pragma unroll
        for (int kk = 0; kk < BK; kk++) {
            float a[8], b[8];
            *(float4*)&a[0] = *(const float4*)&sA[kk][ty * 8];
            *(float4*)&a[4] = *(const float4*)&sA[kk][ty * 8 + 4];
            *(float4*)&b[0] = *(const float4*)&sB[kk][tx * 8];
            *(float4*)&b[4] = *(const float4*)&sB[kk][tx * 8 + 4];
            #pragma unroll
            for (int i = 0; i < 8; i++)
                #pragma unroll
                for (int j = 0; j < 8; j++)
                    acc[i][j] += a[i] * b[j];
        }
    }

    float bb[8];
    #pragma unroll
    for (int j = 0; j < 8; j++) bb[j] = bias[n0 + tx * 8 + j];

    #pragma unroll
    for (int i = 0; i < 8; i++) {
        float* crow = &C[(size_t)(m0 + ty * 8 + i) * OUT_DIM + n0 + tx * 8];
        float4 v0, v1;
        v0.x = acc[i][0] + bb[0]; v0.y = acc[i][1] + bb[1];
        v0.z = acc[i][2] + bb[2]; v0.w = acc[i][3] + bb[3];
        v1.x = acc[i][4] + bb[4]; v1.y = acc[i][5] + bb[5];
        v1.z = acc[i][6] + bb[6]; v1.w = acc[i][7] + bb[7];
        *(float4*)&crow[0] = v0;
        *(float4*)&crow[4] = v1;
    }
}

// ---------------- launch ----------------
extern "C" void kernel_launch(void* const* d_in, const int* in_sizes, int n_in,
                              void* d_out, int out_size)
{
    const float* x    = (const float*)d_in[0];
    const void*  ei   = d_in[1];
    const float* ph   = (const float*)d_in[2];
    const float* Wg   = (const float*)d_in[3];
    const float* bg   = (const float*)d_in[4];
    const float* Wih  = (const float*)d_in[5];
    const float* Whh  = (const float*)d_in[6];
    const float* bih  = (const float*)d_in[7];
    const float* bhh  = (const float*)d_in[8];
    const float* Wlin = (const float*)d_in[9];
    const float* blin = (const float*)d_in[10];
    float* out = (float*)d_out;

    // h_new goes into d_out after logits if there's room, else scratch.
    float* hnew;
    if (out_size >= LOGITS_ELEMS + HNEW_ELEMS) {
        hnew = out + LOGITS_ELEMS;
    } else {
        void* p = nullptr;
        cudaGetSymbolAddress(&p, g_hscratch);
        hnew = (float*)p;
    }

    detect_edge_dtype_kernel<<<1, 256>>>((const int*)ei);

    static int smem_set = 0;
    (void)smem_set;
    cudaFuncSetAttribute(gcn_gru_kernel,
                         cudaFuncAttributeMaxDynamicSharedMemorySize,
                         (int)sizeof(SmemA));
    gcn_gru_kernel<<<2048, 512, sizeof(SmemA)>>>(x, ei, ph, Wg, bg, Wih, Whh,
                                                 bih, bhh, hnew);

    dim3 gridB(NUM_ENVS / BM, OUT_DIM / BN);
    logits_gemm_kernel<<<gridB, 256>>>(hnew, Wlin, blin, out);
}

// round 3
// speedup vs baseline: 3.4349x; 3.4349x over previous
#include <cuda_runtime.h>
#include <cuda_bf16.h>
#include <math.h>

// ---------------- problem constants ----------------
#define NUM_ENVS   16384
#define NUM_AGENTS 16
#define IN_DIM     128
#define GCN_H      64
#define RNN_H      64
#define E_PER      128
#define OUT_DIM    512
#define NNODES     (NUM_ENVS * NUM_AGENTS)           // 262144
#define LOGITS_ELEMS (NUM_ENVS * OUT_DIM)            // 8388608
#define HNEW_ELEMS   (NNODES * RNN_H)                // 16777216

// scratch
__device__ float g_y[NNODES * IN_DIM];      // y = A @ x   (134MB)
__device__ float g_gcn[NNODES * GCN_H];     // gcn_out     (67MB)
__device__ float g_hscratch[HNEW_ELEMS];    // h_new fallback (67MB)

// =====================================================================
// K1: per-env dense GCN operator:  build A_norm, y = A @ x
// =====================================================================
__global__ __launch_bounds__(256)
void gcn_prep_kernel(const float* __restrict__ x_g,
                     const void*  __restrict__ edges,
                     float* __restrict__ y_out)
{
    __shared__ float xs[NUM_AGENTS * IN_DIM];   // 8KB
    __shared__ float As[NUM_AGENTS * NUM_AGENTS];
    __shared__ float ds[NUM_AGENTS];
    __shared__ float dinv[NUM_AGENTS];
    __shared__ int   rs[E_PER];
    __shared__ int   cs[E_PER];
    __shared__ int   s_bad;

    const int tid = threadIdx.x;

    // ---- edge dtype detection (global words 1,3,...,511 all zero => int64) ----
    if (tid == 0) s_bad = 0;
    __syncthreads();
    {
        const int* w = (const int*)edges;
        int bad = 0;
        if (w[2 * tid + 1] != 0) bad = 1;          // tid 0..255 covers words 1..511
        if (bad) atomicOr(&s_bad, 1);
    }
    __syncthreads();
    const int is64 = (s_bad == 0);

    for (int env = blockIdx.x; env < NUM_ENVS; env += gridDim.x) {
        // load x (2048 floats = 512 float4)
        {
            const float4* xg = (const float4*)(x_g + (size_t)env * (NUM_AGENTS * IN_DIM));
            ((float4*)xs)[tid]       = xg[tid];
            ((float4*)xs)[tid + 256] = xg[tid + 256];
        }
        // edges
        if (tid < E_PER) {
            size_t base = (size_t)env * (2 * E_PER);
            int r, c;
            if (is64) {
                const long long* e = (const long long*)edges;
                r = (int)e[base + tid]; c = (int)e[base + E_PER + tid];
            } else {
                const int* e = (const int*)edges;
                r = e[base + tid]; c = e[base + E_PER + tid];
            }
            rs[tid] = r; cs[tid] = c;
        }
        if (tid < NUM_AGENTS) ds[tid] = 1.0f;       // self loop
        As[tid] = 0.0f;                              // 256 cells
        __syncthreads();

        if (tid < E_PER) atomicAdd(&ds[cs[tid]], 1.0f);
        __syncthreads();

        if (tid < NUM_AGENTS) dinv[tid] = rsqrtf(ds[tid]);
        __syncthreads();

        if (tid < E_PER) {
            int r = rs[tid], c = cs[tid];
            atomicAdd(&As[c * NUM_AGENTS + r], dinv[c] * dinv[r]);
        }
        if (tid < NUM_AGENTS)
            atomicAdd(&As[tid * NUM_AGENTS + tid], dinv[tid] * dinv[tid]);
        __syncthreads();

        // y[i][d] = sum_j A[i][j] * x[j][d]
        {
            const int d = tid & 127;
            const int i0 = (tid >> 7) * 8;           // 0 or 8
            float acc[8];
            #pragma unroll
            for (int ii = 0; ii < 8; ii++) acc[ii] = 0.0f;
            #pragma unroll
            for (int j = 0; j < NUM_AGENTS; j++) {
                float xv = xs[j * IN_DIM + d];
                #pragma unroll
                for (int ii = 0; ii < 8; ii++)
                    acc[ii] += As[(i0 + ii) * NUM_AGENTS + j] * xv;
            }
            float* yp = y_out + (size_t)(env * NUM_AGENTS) * IN_DIM;
            #pragma unroll
            for (int ii = 0; ii < 8; ii++)
                yp[(i0 + ii) * IN_DIM + d] = acc[ii];
        }
        __syncthreads();
    }
}

// =====================================================================
// K2: gcn_out = Y @ Wg + bg    (M=262144, K=128, N=64)
// 256 threads, 64-row tiles, 4x4 register tiles, Wg resident in smem
// =====================================================================
#define K2_PITCH 132

__global__ __launch_bounds__(256)
void gcn_gemm_kernel(const float* __restrict__ Y,
                     const float* __restrict__ Wg_g,
                     const float* __restrict__ bg_g,
                     float* __restrict__ gcn_out)
{
    extern __shared__ float sm2[];
    float* Wg = sm2;                       // [128][64]
    float* Yt = sm2 + IN_DIM * GCN_H;      // [64][K2_PITCH]
    float* bg = Yt + 64 * K2_PITCH;        // [64]

    const int tid = threadIdx.x;
    const int tx = tid & 15;               // col group (tx*4)
    const int ty = tid >> 4;               // row group (ty*4)

    // load Wg (8192 floats) + bias
    {
        const float4* wg = (const float4*)Wg_g;
        #pragma unroll
        for (int i = 0; i < 8; i++)
            ((float4*)Wg)[tid + i * 256] = wg[tid + i * 256];
        if (tid < 64) bg[tid] = bg_g[tid];
    }
    __syncthreads();

    const int ntiles = NNODES / 64;
    for (int t = blockIdx.x; t < ntiles; t += gridDim.x) {
        const int m0 = t * 64;
        // load Y tile: 64 rows x 128 -> 2048 float4, 8 per thread
        {
            const float4* yg = (const float4*)(Y + (size_t)m0 * IN_DIM);
            #pragma unroll
            for (int it = 0; it < 8; it++) {
                int idx = tid + it * 256;
                int r = idx >> 5, kq = idx & 31;
                float4 v = yg[(size_t)r * 32 + kq];
                *(float4*)&Yt[r * K2_PITCH + kq * 4] = v;
            }
        }
        __syncthreads();

        float acc[4][4];
        #pragma unroll
        for (int i = 0; i < 4; i++)
            #pragma unroll
            for (int j = 0; j < 4; j++) acc[i][j] = 0.0f;

        #pragma unroll 4
        for (int k0 = 0; k0 < IN_DIM; k0 += 4) {
            float4 a[4], w[4];
            #pragma unroll
            for (int i = 0; i < 4; i++)
                a[i] = *(const float4*)&Yt[(ty * 4 + i) * K2_PITCH + k0];
            #pragma unroll
            for (int kk = 0; kk < 4; kk++)
                w[kk] = *(const float4*)&Wg[(k0 + kk) * GCN_H + tx * 4];
            #pragma unroll
            for (int kk = 0; kk < 4; kk++) {
                #pragma unroll
                for (int i = 0; i < 4; i++) {
                    float av = (kk == 0) ? a[i].x : (kk == 1) ? a[i].y : (kk == 2) ? a[i].z : a[i].w;
                    acc[i][0] += av * w[kk].x;
                    acc[i][1] += av * w[kk].y;
                    acc[i][2] += av * w[kk].z;
                    acc[i][3] += av * w[kk].w;
                }
            }
        }

        float4 bb = *(const float4*)&bg[tx * 4];
        #pragma unroll
        for (int i = 0; i < 4; i++) {
            float4 v;
            v.x = acc[i][0] + bb.x; v.y = acc[i][1] + bb.y;
            v.z = acc[i][2] + bb.z; v.w = acc[i][3] + bb.w;
            *(float4*)&gcn_out[(size_t)(m0 + ty * 4 + i) * GCN_H + tx * 4] = v;
        }
        __syncthreads();
    }
}

// =====================================================================
// K3: GRU  (gx = gcn@WihT, gh = h@WhhT, fused elementwise -> h_new)
// 512 threads, 128-row tiles, per-thread 4 rows x 4 feats x {r,z,nx,nh}
// =====================================================================
#define K3_PITCH 68

__global__ __launch_bounds__(512)
void gru_kernel(const float* __restrict__ gcn,
                const float* __restrict__ prevh,
                const float* __restrict__ Wih_g,
                const float* __restrict__ Whh_g,
                const float* __restrict__ bih_g,
                const float* __restrict__ bhh_g,
                float* __restrict__ hnew)
{
    extern __shared__ float sm3[];
    float* Wih = sm3;                          // [64][192] (k-major)
    float* Whh = Wih + 64 * 192;
    float* gt  = Whh + 64 * 192;               // [128][K3_PITCH]
    float* ht  = gt + 128 * K3_PITCH;
    float* bsum = ht + 128 * K3_PITCH;         // [128] bih+bhh for r,z
    float* bnx  = bsum + 128;                  // [64]
    float* bnh  = bnx + 64;                    // [64]

    const int tid = threadIdx.x;
    const int tx = tid & 15;                   // feat group f = tx*4
    const int ty = tid >> 4;                   // 0..31, rows ty*4..ty*4+3
    const int f4 = tx * 4;

    // transpose-load weights: W[j][k] -> Ws[k*192 + j]
    for (int idx = tid; idx < 192 * 64; idx += 512) {
        int j = idx % 192, k = idx / 192;
        Wih[k * 192 + j] = Wih_g[j * 64 + k];
        Whh[k * 192 + j] = Whh_g[j * 64 + k];
    }
    if (tid < 128) bsum[tid] = bih_g[tid] + bhh_g[tid];
    else if (tid < 192) { bnx[tid - 128] = bih_g[tid]; bnh[tid - 128] = bhh_g[tid]; }
    __syncthreads();

    const int ntiles = NNODES / 128;
    for (int t = blockIdx.x; t < ntiles; t += gridDim.x) {
        const int m0 = t * 128;
        // load tiles: 128 rows x 64 = 2048 float4 each, 4/thread
        {
            const float4* gg = (const float4*)(gcn + (size_t)m0 * RNN_H);
            const float4* hg = (const float4*)(prevh + (size_t)m0 * RNN_H);
            #pragma unroll
            for (int it = 0; it < 4; it++) {
                int idx = tid + it * 512;
                int r = idx >> 4, c4 = (idx & 15) * 4;
                float4 gv = gg[idx];
                float4 hv = hg[idx];
                *(float4*)&gt[r * K3_PITCH + c4] = gv;
                *(float4*)&ht[r * K3_PITCH + c4] = hv;
            }
        }
        __syncthreads();

        float aR[4][4], aZ[4][4], aNx[4][4], aNh[4][4];
        #pragma unroll
        for (int i = 0; i < 4; i++)
            #pragma unroll
            for (int j = 0; j < 4; j++) { aR[i][j]=0.f; aZ[i][j]=0.f; aNx[i][j]=0.f; aNh[i][j]=0.f; }

        // x-side: K=64 over gcn tile with Wih
        #pragma unroll 2
        for (int k0 = 0; k0 < RNN_H; k0 += 4) {
            float4 a[4];
            #pragma unroll
            for (int i = 0; i < 4; i++)
                a[i] = *(const float4*)&gt[(ty * 4 + i) * K3_PITCH + k0];
            #pragma unroll
            for (int kk = 0; kk < 4; kk++) {
                const float* wrow = &Wih[(k0 + kk) * 192];
                float4 wr = *(const float4*)&wrow[f4];
                float4 wz = *(const float4*)&wrow[64 + f4];
                float4 wn = *(const float4*)&wrow[128 + f4];
                #pragma unroll
                for (int i = 0; i < 4; i++) {
                    float av = (kk==0)?a[i].x:(kk==1)?a[i].y:(kk==2)?a[i].z:a[i].w;
                    aR[i][0]+=av*wr.x; aR[i][1]+=av*wr.y; aR[i][2]+=av*wr.z; aR[i][3]+=av*wr.w;
                    aZ[i][0]+=av*wz.x; aZ[i][1]+=av*wz.y; aZ[i][2]+=av*wz.z; aZ[i][3]+=av*wz.w;
                    aNx[i][0]+=av*wn.x; aNx[i][1]+=av*wn.y; aNx[i][2]+=av*wn.z; aNx[i][3]+=av*wn.w;
                }
            }
        }
        // h-side: K=64 over h tile with Whh (r,z accumulate; n separate)
        #pragma unroll 2
        for (int k0 = 0; k0 < RNN_H; k0 += 4) {
            float4 a[4];
            #pragma unroll
            for (int i = 0; i < 4; i++)
                a[i] = *(const float4*)&ht[(ty * 4 + i) * K3_PITCH + k0];
            #pragma unroll
            for (int kk = 0; kk < 4; kk++) {
                const float* wrow = &Whh[(k0 + kk) * 192];
                float4 wr = *(const float4*)&wrow[f4];
                float4 wz = *(const float4*)&wrow[64 + f4];
                float4 wn = *(const float4*)&wrow[128 + f4];
                #pragma unroll
                for (int i = 0; i < 4; i++) {
                    float av = (kk==0)?a[i].x:(kk==1)?a[i].y:(kk==2)?a[i].z:a[i].w;
                    aR[i][0]+=av*wr.x; aR[i][1]+=av*wr.y; aR[i][2]+=av*wr.z; aR[i][3]+=av*wr.w;
                    aZ[i][0]+=av*wz.x; aZ[i][1]+=av*wz.y; aZ[i][2]+=av*wz.z; aZ[i][3]+=av*wz.w;
                    aNh[i][0]+=av*wn.x; aNh[i][1]+=av*wn.y; aNh[i][2]+=av*wn.z; aNh[i][3]+=av*wn.w;
                }
            }
        }

        // combine + write
        float4 brz0 = *(const float4*)&bsum[f4];
        float4 brz1 = *(const float4*)&bsum[64 + f4];
        float4 bx   = *(const float4*)&bnx[f4];
        float4 bh   = *(const float4*)&bnh[f4];
        #pragma unroll
        for (int i = 0; i < 4; i++) {
            int row = ty * 4 + i;
            float4 hv = *(const float4*)&ht[row * K3_PITCH + f4];
            float4 outv;
            {
                float r = 1.0f / (1.0f + __expf(-(aR[i][0] + brz0.x)));
                float z = 1.0f / (1.0f + __expf(-(aZ[i][0] + brz1.x)));
                float n = tanhf(aNx[i][0] + bx.x + r * (aNh[i][0] + bh.x));
                outv.x = (1.0f - z) * n + z * hv.x;
            }
            {
                float r = 1.0f / (1.0f + __expf(-(aR[i][1] + brz0.y)));
                float z = 1.0f / (1.0f + __expf(-(aZ[i][1] + brz1.y)));
                float n = tanhf(aNx[i][1] + bx.y + r * (aNh[i][1] + bh.y));
                outv.y = (1.0f - z) * n + z * hv.y;
            }
            {
                float r = 1.0f / (1.0f + __expf(-(aR[i][2] + brz0.z)));
                float z = 1.0f / (1.0f + __expf(-(aZ[i][2] + brz1.z)));
                float n = tanhf(aNx[i][2] + bx.z + r * (aNh[i][2] + bh.z));
                outv.z = (1.0f - z) * n + z * hv.z;
            }
            {
                float r = 1.0f / (1.0f + __expf(-(aR[i][3] + brz0.w)));
                float z = 1.0f / (1.0f + __expf(-(aZ[i][3] + brz1.w)));
                float n = tanhf(aNx[i][3] + bx.w + r * (aNh[i][3] + bh.w));
                outv.w = (1.0f - z) * n + z * hv.w;
            }
            *(float4*)&hnew[(size_t)(m0 + row) * RNN_H + f4] = outv;
        }
        __syncthreads();
    }
}

// =====================================================================
// K4: logits = h_new @ W_lin^T + b   (unchanged from R0)
// =====================================================================
#define BM 128
#define BN 128
#define BK 16

__global__ __launch_bounds__(256)
void logits_gemm_kernel(const float* __restrict__ A,
                        const float* __restrict__ W,
                        const float* __restrict__ bias,
                        float* __restrict__ C)
{
    __shared__ float sA[BK][BM];
    __shared__ float sB[BK][BN];

    const int tid = threadIdx.x;
    const int m0 = blockIdx.x * BM;
    const int n0 = blockIdx.y * BN;
    const int tx = tid & 15;
    const int ty = tid >> 4;

    const int lrow = tid >> 2;
    const int lk   = (tid & 3) * 4;

    float acc[8][8];
    #pragma unroll
    for (int i = 0; i < 8; i++)
        #pragma unroll
        for (int j = 0; j < 8; j++) acc[i][j] = 0.0f;

    for (int k0 = 0; k0 < NUM_AGENTS * RNN_H; k0 += BK) {
        float4 av0 = *(const float4*)&A[(size_t)(m0 + lrow)      * 1024 + k0 + lk];
        float4 av1 = *(const float4*)&A[(size_t)(m0 + lrow + 64) * 1024 + k0 + lk];
        float4 bv0 = *(const float4*)&W[(size_t)(n0 + lrow)      * 1024 + k0 + lk];
        float4 bv1 = *(const float4*)&W[(size_t)(n0 + lrow + 64) * 1024 + k0 + lk];
        __syncthreads();
        sA[lk + 0][lrow] = av0.x; sA[lk + 1][lrow] = av0.y;
        sA[lk + 2][lrow] = av0.z; sA[lk + 3][lrow] = av0.w;
        sA[lk + 0][lrow + 64] = av1.x; sA[lk + 1][lrow + 64] = av1.y;
        sA[lk + 2][lrow + 64] = av1.z; sA[lk + 3][lrow + 64] = av1.w;
        sB[lk + 0][lrow] = bv0.x; sB[lk + 1][lrow] = bv0.y;
        sB[lk + 2][lrow] = bv0.z; sB[lk + 3][lrow] = bv0.w;
        sB[lk + 0][lrow + 64] = bv1.x; sB[lk + 1][lrow + 64] = bv1.y;
        sB[lk + 2][lrow + 64] = bv1.z; sB[lk + 3][lrow + 64] = bv1.w;
        __syncthreads();

        #pragma unroll
        for (int kk = 0; kk < BK; kk++) {
            float a[8], b[8];
            *(float4*)&a[0] = *(const float4*)&sA[kk][ty * 8];
            *(float4*)&a[4] = *(const float4*)&sA[kk][ty * 8 + 4];
            *(float4*)&b[0] = *(const float4*)&sB[kk][tx * 8];
            *(float4*)&b[4] = *(const float4*)&sB[kk][tx * 8 + 4];
            #pragma unroll
            for (int i = 0; i < 8; i++)
                #pragma unroll
                for (int j = 0; j < 8; j++)
                    acc[i][j] += a[i] * b[j];
        }
    }

    float bb[8];
    #pragma unroll
    for (int j = 0; j < 8; j++) bb[j] = bias[n0 + tx * 8 + j];

    #pragma unroll
    for (int i = 0; i < 8; i++) {
        float* crow = &C[(size_t)(m0 + ty * 8 + i) * OUT_DIM + n0 + tx * 8];
        float4 v0, v1;
        v0.x = acc[i][0] + bb[0]; v0.y = acc[i][1] + bb[1];
        v0.z = acc[i][2] + bb[2]; v0.w = acc[i][3] + bb[3];
        v1.x = acc[i][4] + bb[4]; v1.y = acc[i][5] + bb[5];
        v1.z = acc[i][6] + bb[6]; v1.w = acc[i][7] + bb[7];
        *(float4*)&crow[0] = v0;
        *(float4*)&crow[4] = v1;
    }
}

// ---------------- launch ----------------
extern "C" void kernel_launch(void* const* d_in, const int* in_sizes, int n_in,
                              void* d_out, int out_size)
{
    const float* x    = (const float*)d_in[0];
    const void*  ei   = d_in[1];
    const float* ph   = (const float*)d_in[2];
    const float* Wg   = (const float*)d_in[3];
    const float* bg   = (const float*)d_in[4];
    const float* Wih  = (const float*)d_in[5];
    const float* Whh  = (const float*)d_in[6];
    const float* bih  = (const float*)d_in[7];
    const float* bhh  = (const float*)d_in[8];
    const float* Wlin = (const float*)d_in[9];
    const float* blin = (const float*)d_in[10];
    float* out = (float*)d_out;

    float* yb;   { void* p; cudaGetSymbolAddress(&p, g_y);   yb  = (float*)p; }
    float* gcn;  { void* p; cudaGetSymbolAddress(&p, g_gcn); gcn = (float*)p; }

    float* hnew;
    if (out_size >= LOGITS_ELEMS + HNEW_ELEMS) {
        hnew = out + LOGITS_ELEMS;
    } else {
        void* p = nullptr;
        cudaGetSymbolAddress(&p, g_hscratch);
        hnew = (float*)p;
    }

    // K1: build per-env operator, y = A @ x
    gcn_prep_kernel<<<2048, 256>>>(x, ei, yb);

    // K2: gcn_out = y @ Wg + bg
    {
        int smem = (IN_DIM * GCN_H + 64 * K2_PITCH + 64) * sizeof(float);
        cudaFuncSetAttribute(gcn_gemm_kernel,
                             cudaFuncAttributeMaxDynamicSharedMemorySize, smem);
        gcn_gemm_kernel<<<444, 256, smem>>>(yb, Wg, bg, gcn);
    }

    // K3: GRU -> h_new
    {
        int smem = (2 * 64 * 192 + 2 * 128 * K3_PITCH + 128 + 64 + 64) * sizeof(float);
        cudaFuncSetAttribute(gru_kernel,
                             cudaFuncAttributeMaxDynamicSharedMemorySize, smem);
        gru_kernel<<<148, 512, smem>>>(gcn, ph, Wih, Whh, bih, bhh, hnew);
    }

    // K4: logits
    dim3 gridB(NUM_ENVS / BM, OUT_DIM / BN);
    logits_gemm_kernel<<<gridB, 256>>>(hnew, Wlin, blin, out);
}